// round 1
// baseline (speedup 1.0000x reference)
#include <cuda_runtime.h>
#include <math.h>

#define SEQ 2048
#define DIM 2048
#define NH 16
#define HDIM 128

// Scratch (allocation-free rule: __device__ globals)
__device__ float g_Q[SEQ * DIM];
__device__ float g_K[SEQ * DIM];
__device__ float g_V[SEQ * DIM];
__device__ float g_G[SEQ * DIM];
__device__ float g_Y[SEQ * DIM];
__device__ float g_GT[SEQ * DIM];

// ---------------------------------------------------------------------------
// SGEMM-TN: C[M][N] = sum_k A[m][k] * B[n][k], M=N=K=2048, fp32.
// 128x128 block tile, BK=16, 256 threads, 8x8 per-thread microtile.
// ---------------------------------------------------------------------------
__global__ __launch_bounds__(256) void sgemm_tn(const float* __restrict__ A,
                                                const float* __restrict__ B,
                                                float* __restrict__ C) {
    const int BM = 128, BK = 16;
    const int LDA = BM + 4;  // pad to break store-phase bank conflicts
    __shared__ float As[BK][LDA];
    __shared__ float Bs[BK][LDA];

    int tid = threadIdx.x;
    int m0 = blockIdx.y * BM;
    int n0 = blockIdx.x * BM;
    int tx = tid & 15, ty = tid >> 4;

    float acc[8][8];
#pragma unroll
    for (int i = 0; i < 8; i++)
#pragma unroll
        for (int j = 0; j < 8; j++) acc[i][j] = 0.f;

    for (int k0 = 0; k0 < DIM; k0 += BK) {
#pragma unroll
        for (int i = 0; i < 2; i++) {
            int idx = tid + i * 256;          // 0..511
            int row = idx >> 2;               // 0..127
            int c4 = (idx & 3) * 4;           // 0,4,8,12
            float4 va = *(const float4*)(A + (size_t)(m0 + row) * DIM + k0 + c4);
            As[c4 + 0][row] = va.x; As[c4 + 1][row] = va.y;
            As[c4 + 2][row] = va.z; As[c4 + 3][row] = va.w;
            float4 vb = *(const float4*)(B + (size_t)(n0 + row) * DIM + k0 + c4);
            Bs[c4 + 0][row] = vb.x; Bs[c4 + 1][row] = vb.y;
            Bs[c4 + 2][row] = vb.z; Bs[c4 + 3][row] = vb.w;
        }
        __syncthreads();
#pragma unroll
        for (int k = 0; k < BK; k++) {
            float a[8], b[8];
            *(float4*)&a[0] = *(const float4*)&As[k][ty * 8];
            *(float4*)&a[4] = *(const float4*)&As[k][ty * 8 + 4];
            *(float4*)&b[0] = *(const float4*)&Bs[k][tx * 4];
            *(float4*)&b[4] = *(const float4*)&Bs[k][64 + tx * 4];
#pragma unroll
            for (int i = 0; i < 8; i++)
#pragma unroll
                for (int j = 0; j < 8; j++) acc[i][j] += a[i] * b[j];
        }
        __syncthreads();
    }

#pragma unroll
    for (int i = 0; i < 8; i++) {
        float4 r0 = make_float4(acc[i][0], acc[i][1], acc[i][2], acc[i][3]);
        float4 r1 = make_float4(acc[i][4], acc[i][5], acc[i][6], acc[i][7]);
        float* c = C + (size_t)(m0 + ty * 8 + i) * DIM + n0;
        *(float4*)(c + tx * 4) = r0;
        *(float4*)(c + 64 + tx * 4) = r1;
    }
}

// ---------------------------------------------------------------------------
// Retention attention, causal, per-head decay gamma^(i-j).
// grid = (S/32 i-tiles, H heads), 256 threads (8 warps).
// Per block: stage Q tile [128d][32i] (transposed, padded), loop j-tiles:
//   stage K [128d][32j] -> s = q.k^T * scale * decay -> stage V [32j][128d]
//   (same buffer) -> y += s.V.  All smem reads bank-conflict-free on the
//   compute path.
// ---------------------------------------------------------------------------
__global__ __launch_bounds__(256) void retention_attn() {
    const int BI = 32, BJ = 32;
    const int QLD = 36;  // padded i-stride for [d][i] layout
    __shared__ float Qs[HDIM * QLD];          // Qs[d*36 + i]
    __shared__ float KV[HDIM * QLD];          // K phase: [d*36+j]; V phase: [j*128+d]
    __shared__ float Ss[BI * BJ];             // Ss[i*32 + j]

    int head = blockIdx.y;
    int i0 = blockIdx.x * BI;
    int tid = threadIdx.x;
    int lane = tid & 31;
    int w = tid >> 5;  // warp 0..7, owns rows w*4..w*4+3

    // gammas = 1 - exp(linspace(log(1/32), log(1/512), 16))
    const float lg0 = -3.4657359027997265f;
    const float lg1 = -6.2383246250395075f;
    float gamma = 1.0f - expf(lg0 + (lg1 - lg0) * ((float)head * (1.0f / 15.0f)));
    float log2g = log2f(gamma);
    const float scale = 0.088388347648318447f;  // 128^-0.5

    const float* Qh = g_Q + head * HDIM;
    const float* Kh = g_K + head * HDIM;
    const float* Vh = g_V + head * HDIM;

    // Stage Q tile (transposed into [d][i])
    for (int t = tid; t < BI * HDIM / 4; t += 256) {
        int i = t >> 5;           // 0..31
        int d4 = (t & 31) * 4;    // 0..124
        float4 v = *(const float4*)(Qh + (size_t)(i0 + i) * DIM + d4);
        Qs[(d4 + 0) * QLD + i] = v.x; Qs[(d4 + 1) * QLD + i] = v.y;
        Qs[(d4 + 2) * QLD + i] = v.z; Qs[(d4 + 3) * QLD + i] = v.w;
    }

    float yacc[4][4];
#pragma unroll
    for (int r = 0; r < 4; r++)
#pragma unroll
        for (int q = 0; q < 4; q++) yacc[r][q] = 0.f;

    int nj = blockIdx.x + 1;  // causal: j-tiles 0..i-tile inclusive
    for (int jt = 0; jt < nj; jt++) {
        int j0 = jt * BJ;
        __syncthreads();  // protect KV reuse (and Qs on first iter)
        // Stage K tile transposed [d][j]
        for (int t = tid; t < BJ * HDIM / 4; t += 256) {
            int j = t >> 5;
            int d4 = (t & 31) * 4;
            float4 v = *(const float4*)(Kh + (size_t)(j0 + j) * DIM + d4);
            KV[(d4 + 0) * QLD + j] = v.x; KV[(d4 + 1) * QLD + j] = v.y;
            KV[(d4 + 2) * QLD + j] = v.z; KV[(d4 + 3) * QLD + j] = v.w;
        }
        __syncthreads();

        // Phase 1: s[i][j], warp w rows w*4..+3, lane = column j
        float sacc[4] = {0.f, 0.f, 0.f, 0.f};
#pragma unroll 4
        for (int d = 0; d < HDIM; d++) {
            float kv = KV[d * QLD + lane];
            float4 qv = *(const float4*)&Qs[d * QLD + w * 4];  // broadcast in warp
            sacc[0] += qv.x * kv;
            sacc[1] += qv.y * kv;
            sacc[2] += qv.z * kv;
            sacc[3] += qv.w * kv;
        }
        int jg = j0 + lane;
#pragma unroll
        for (int r = 0; r < 4; r++) {
            int ig = i0 + w * 4 + r;
            int diff = ig - jg;
            float f = (diff >= 0) ? scale * exp2f(log2g * (float)diff) : 0.0f;
            Ss[(w * 4 + r) * BJ + lane] = sacc[r] * f;
        }
        __syncthreads();  // phase-1 K reads done; Ss visible (same-warp anyway)

        // Stage V tile [j][d] into the same buffer
        for (int t = tid; t < BJ * HDIM / 4; t += 256) {
            int j = t >> 5;
            int d4 = (t & 31) * 4;
            float4 v = *(const float4*)(Vh + (size_t)(j0 + j) * DIM + d4);
            *(float4*)&KV[j * HDIM + d4] = v;
        }
        __syncthreads();

        // Phase 2: y[i][c] += s[i][j] * V[j][c]; rows w*4+r, cols lane+32q
#pragma unroll 4
        for (int j = 0; j < BJ; j++) {
            float sv0 = Ss[(w * 4 + 0) * BJ + j];
            float sv1 = Ss[(w * 4 + 1) * BJ + j];
            float sv2 = Ss[(w * 4 + 2) * BJ + j];
            float sv3 = Ss[(w * 4 + 3) * BJ + j];
#pragma unroll
            for (int q = 0; q < 4; q++) {
                float vv = KV[j * HDIM + lane + 32 * q];
                yacc[0][q] += sv0 * vv;
                yacc[1][q] += sv1 * vv;
                yacc[2][q] += sv2 * vv;
                yacc[3][q] += sv3 * vv;
            }
        }
    }

    // Write Y (coalesced: lane contiguous)
#pragma unroll
    for (int r = 0; r < 4; r++) {
        float* yp = g_Y + (size_t)(i0 + w * 4 + r) * DIM + head * HDIM;
#pragma unroll
        for (int q = 0; q < 4; q++) yp[lane + 32 * q] = yacc[r][q];
    }
}

// ---------------------------------------------------------------------------
// Row-wise LayerNorm over Y, then * silu(G) -> g_GT. One block per row.
// ---------------------------------------------------------------------------
__global__ __launch_bounds__(256) void ln_silu_gate(const float* __restrict__ lnw,
                                                    const float* __restrict__ lnb) {
    int row = blockIdx.x;
    const float* y = g_Y + (size_t)row * DIM;
    const float* g = g_G + (size_t)row * DIM;
    float* o = g_GT + (size_t)row * DIM;
    int tid = threadIdx.x;

    float vals[8];
    float s = 0.f, ss = 0.f;
#pragma unroll
    for (int i = 0; i < 2; i++) {
        float4 v = *(const float4*)(y + tid * 4 + i * 1024);
        vals[i * 4 + 0] = v.x; vals[i * 4 + 1] = v.y;
        vals[i * 4 + 2] = v.z; vals[i * 4 + 3] = v.w;
        s += v.x + v.y + v.z + v.w;
        ss += v.x * v.x + v.y * v.y + v.z * v.z + v.w * v.w;
    }
#pragma unroll
    for (int off = 16; off > 0; off >>= 1) {
        s += __shfl_xor_sync(0xFFFFFFFFu, s, off);
        ss += __shfl_xor_sync(0xFFFFFFFFu, ss, off);
    }
    __shared__ float rs[8], rss[8];
    if ((tid & 31) == 0) { rs[tid >> 5] = s; rss[tid >> 5] = ss; }
    __syncthreads();
    s = 0.f; ss = 0.f;
#pragma unroll
    for (int i = 0; i < 8; i++) { s += rs[i]; ss += rss[i]; }

    float mu = s * (1.0f / DIM);
    float var = ss * (1.0f / DIM) - mu * mu;
    float rstd = rsqrtf(var + 1e-5f);

#pragma unroll
    for (int i = 0; i < 2; i++) {
        int c0 = tid * 4 + i * 1024;
        float4 gv = *(const float4*)(g + c0);
        float4 wv = *(const float4*)(lnw + c0);
        float4 bv = *(const float4*)(lnb + c0);
        float4 out;
        float yn;
        yn = (vals[i * 4 + 0] - mu) * rstd * wv.x + bv.x;
        out.x = yn * (gv.x / (1.0f + expf(-gv.x)));
        yn = (vals[i * 4 + 1] - mu) * rstd * wv.y + bv.y;
        out.y = yn * (gv.y / (1.0f + expf(-gv.y)));
        yn = (vals[i * 4 + 2] - mu) * rstd * wv.z + bv.z;
        out.z = yn * (gv.z / (1.0f + expf(-gv.z)));
        yn = (vals[i * 4 + 3] - mu) * rstd * wv.w + bv.w;
        out.w = yn * (gv.w / (1.0f + expf(-gv.w)));
        *(float4*)(o + c0) = out;
    }
}

// ---------------------------------------------------------------------------
extern "C" void kernel_launch(void* const* d_in, const int* in_sizes, int n_in,
                              void* d_out, int out_size) {
    const float* x   = (const float*)d_in[0];
    const float* wq  = (const float*)d_in[1];
    const float* wk  = (const float*)d_in[2];
    const float* wv  = (const float*)d_in[3];
    const float* wg  = (const float*)d_in[4];
    const float* wo  = (const float*)d_in[5];
    const float* lnw = (const float*)d_in[6];
    const float* lnb = (const float*)d_in[7];
    float* out = (float*)d_out;

    float *Q, *K, *V, *G, *GT;
    cudaGetSymbolAddress((void**)&Q,  g_Q);
    cudaGetSymbolAddress((void**)&K,  g_K);
    cudaGetSymbolAddress((void**)&V,  g_V);
    cudaGetSymbolAddress((void**)&G,  g_G);
    cudaGetSymbolAddress((void**)&GT, g_GT);

    dim3 gemm_grid(DIM / 128, SEQ / 128);
    sgemm_tn<<<gemm_grid, 256>>>(x, wq, Q);
    sgemm_tn<<<gemm_grid, 256>>>(x, wk, K);
    sgemm_tn<<<gemm_grid, 256>>>(x, wv, V);
    sgemm_tn<<<gemm_grid, 256>>>(x, wg, G);

    retention_attn<<<dim3(SEQ / 32, NH), 256>>>();

    ln_silu_gate<<<SEQ, 256>>>(lnw, lnb);

    sgemm_tn<<<gemm_grid, 256>>>(GT, wo, out);
}

// round 4
// speedup vs baseline: 1.2901x; 1.2901x over previous
#include <cuda_runtime.h>
#include <cuda_bf16.h>
#include <math.h>
#include <cstdint>

#define SEQ 2048
#define DIM 2048
#define NH 16
#define HDIM 128

// ------------------------- scratch (device globals) -------------------------
__device__ float g_Q[SEQ * DIM];
__device__ float g_K[SEQ * DIM];
__device__ float g_V[SEQ * DIM];
__device__ float g_G[SEQ * DIM];
__device__ float g_Y[SEQ * DIM];

// separate hi / lo bf16 buffers, all [rows][2048]
__device__ __nv_bfloat16 g_xhi[SEQ * DIM],  g_xlo[SEQ * DIM];
__device__ __nv_bfloat16 g_wqhi[DIM * DIM], g_wqlo[DIM * DIM];
__device__ __nv_bfloat16 g_wkhi[DIM * DIM], g_wklo[DIM * DIM];
__device__ __nv_bfloat16 g_wvhi[DIM * DIM], g_wvlo[DIM * DIM];
__device__ __nv_bfloat16 g_wghi[DIM * DIM], g_wglo[DIM * DIM];
__device__ __nv_bfloat16 g_wohi[DIM * DIM], g_wolo[DIM * DIM];
__device__ __nv_bfloat16 g_ahi[SEQ * DIM],  g_alo[SEQ * DIM];

// ------------------------- helpers -------------------------
__device__ __forceinline__ uint32_t smem_u32(const void* p) {
    uint32_t a;
    asm("{ .reg .u64 t; cvta.to.shared.u64 t, %1; cvt.u32.u64 %0, t; }" : "=r"(a) : "l"(p));
    return a;
}
__device__ __forceinline__ void cp16(uint32_t dst, const void* src) {
    asm volatile("cp.async.cg.shared.global [%0], [%1], 16;" :: "r"(dst), "l"(src));
}
__device__ __forceinline__ void ldx4(uint32_t* r, uint32_t addr) {
    asm volatile("ldmatrix.sync.aligned.m8n8.x4.shared.b16 {%0,%1,%2,%3}, [%4];"
                 : "=r"(r[0]), "=r"(r[1]), "=r"(r[2]), "=r"(r[3]) : "r"(addr));
}
__device__ __forceinline__ void mma16816(float* c, const uint32_t* a, uint32_t b0, uint32_t b1) {
    asm volatile(
        "mma.sync.aligned.m16n8k16.row.col.f32.bf16.bf16.f32 "
        "{%0,%1,%2,%3}, {%4,%5,%6,%7}, {%8,%9}, {%0,%1,%2,%3};"
        : "+f"(c[0]), "+f"(c[1]), "+f"(c[2]), "+f"(c[3])
        : "r"(a[0]), "r"(a[1]), "r"(a[2]), "r"(a[3]), "r"(b0), "r"(b1));
}

// ---------------------------------------------------------------------------
// bf16 GEMM (TN): C[M][N] (+)= sum_k A[m][k]*B[n][k], M=N=K=2048.
// Tile 128x128, BK=64, 8 warps (2x4), warp 64x32, double-buffered cp.async.
// accum=0: overwrite C; accum=1: C += result.
// ---------------------------------------------------------------------------
static constexpr int GBM = 128, GBN = 128, GBK = 64;
static constexpr int NCH = DIM / GBK;       // 32 chunks
static constexpr int ATILE = GBM * GBK * 2; // 16384 B
static constexpr int BTILE = GBN * GBK * 2; // 16384 B
static constexpr int GBUF = ATILE + BTILE;  // 32768 B
static constexpr int GEMM_SMEM = 2 * GBUF;  // 65536 B

__device__ __forceinline__ void load_tile(uint32_t buf,
                                          const __nv_bfloat16* __restrict__ A,
                                          const __nv_bfloat16* __restrict__ B,
                                          int m0, int n0, int kc, int tid) {
#pragma unroll
    for (int it = 0; it < 4; it++) {
        int idx = tid + it * 256;
        int r = idx >> 3, c = idx & 7;
        uint32_t phys = buf + r * 128 + (((c ^ (r & 7))) << 4);
        cp16(phys, A + (size_t)(m0 + r) * DIM + kc + c * 8);
    }
#pragma unroll
    for (int it = 0; it < 4; it++) {
        int idx = tid + it * 256;
        int r = idx >> 3, c = idx & 7;
        uint32_t phys = buf + ATILE + r * 128 + (((c ^ (r & 7))) << 4);
        cp16(phys, B + (size_t)(n0 + r) * DIM + kc + c * 8);
    }
}

__global__ __launch_bounds__(256, 1) void gemm_bf16(const __nv_bfloat16* __restrict__ A,
                                                    const __nv_bfloat16* __restrict__ B,
                                                    float* __restrict__ C, int accum) {
    extern __shared__ char smem[];
    uint32_t sb = smem_u32(smem);
    int tid = threadIdx.x;
    int wid = tid >> 5, lane = tid & 31;
    int wm = wid & 1, wn = wid >> 1;          // 2 x 4 warp grid
    int m0 = blockIdx.y * GBM, n0 = blockIdx.x * GBN;

    int a_mh = (lane >> 3) & 1, a_kh = lane >> 4, lr = lane & 7;
    uint32_t aOff[4]; int aR7[4];
#pragma unroll
    for (int i = 0; i < 4; i++) {
        int row = wm * 64 + i * 16 + a_mh * 8 + lr;
        aOff[i] = row * 128; aR7[i] = row & 7;
    }
    int b_jl = lane >> 4, b_kh = (lane >> 3) & 1;
    uint32_t bOff[2]; int bR7[2];
#pragma unroll
    for (int p = 0; p < 2; p++) {
        int row = wn * 32 + p * 16 + b_jl * 8 + lr;
        bOff[p] = row * 128; bR7[p] = row & 7;
    }

    float acc[4][4][4];
#pragma unroll
    for (int i = 0; i < 4; i++)
#pragma unroll
        for (int j = 0; j < 4; j++)
#pragma unroll
            for (int q = 0; q < 4; q++) acc[i][j][q] = 0.f;

    load_tile(sb, A, B, m0, n0, 0, tid);
    asm volatile("cp.async.commit_group;" ::: "memory");

    for (int t = 0; t < NCH; t++) {
        if (t + 1 < NCH) {
            load_tile(sb + ((t + 1) & 1) * GBUF, A, B, m0, n0, (t + 1) * GBK, tid);
            asm volatile("cp.async.commit_group;" ::: "memory");
            asm volatile("cp.async.wait_group 1;" ::: "memory");
        } else {
            asm volatile("cp.async.wait_group 0;" ::: "memory");
        }
        __syncthreads();

        uint32_t bufA = sb + (t & 1) * GBUF;
        uint32_t bufB = bufA + ATILE;
#pragma unroll
        for (int ks = 0; ks < 4; ks++) {
            uint32_t a[4][4], b[2][4];
            int ca = ks * 2 + a_kh;
            int cb = ks * 2 + b_kh;
#pragma unroll
            for (int i = 0; i < 4; i++)
                ldx4(a[i], bufA + aOff[i] + (((uint32_t)(ca ^ aR7[i])) << 4));
#pragma unroll
            for (int p = 0; p < 2; p++)
                ldx4(b[p], bufB + bOff[p] + (((uint32_t)(cb ^ bR7[p])) << 4));
#pragma unroll
            for (int i = 0; i < 4; i++)
#pragma unroll
                for (int j = 0; j < 4; j++) {
                    int p = j >> 1, jl = j & 1;
                    mma16816(acc[i][j], a[i], b[p][2 * jl], b[p][2 * jl + 1]);
                }
        }
        __syncthreads();
    }

    // epilogue (optionally accumulating into C)
    int qr = lane >> 2, qc = (lane & 3) * 2;
#pragma unroll
    for (int i = 0; i < 4; i++) {
        int mrow = m0 + wm * 64 + i * 16 + qr;
#pragma unroll
        for (int j = 0; j < 4; j++) {
            float* cp = C + (size_t)mrow * DIM + n0 + wn * 32 + j * 8 + qc;
            if (accum) {
                cp[0]           += acc[i][j][0];
                cp[1]           += acc[i][j][1];
                cp[8 * DIM]     += acc[i][j][2];
                cp[8 * DIM + 1] += acc[i][j][3];
            } else {
                cp[0]           = acc[i][j][0];
                cp[1]           = acc[i][j][1];
                cp[8 * DIM]     = acc[i][j][2];
                cp[8 * DIM + 1] = acc[i][j][3];
            }
        }
    }
}

// ---------------------------------------------------------------------------
// fp32 -> separate bf16 hi and lo arrays (flat, same indexing as source)
// ---------------------------------------------------------------------------
__global__ __launch_bounds__(256) void cvt_split(const float* __restrict__ s,
                                                 __nv_bfloat16* __restrict__ hi,
                                                 __nv_bfloat16* __restrict__ lo, int n4) {
    int i = blockIdx.x * 256 + threadIdx.x;
    if (i >= n4) return;
    float4 v = ((const float4*)s)[i];
    __nv_bfloat16 h0 = __float2bfloat16(v.x), h1 = __float2bfloat16(v.y);
    __nv_bfloat16 h2 = __float2bfloat16(v.z), h3 = __float2bfloat16(v.w);
    __nv_bfloat16 l0 = __float2bfloat16(v.x - __bfloat162float(h0));
    __nv_bfloat16 l1 = __float2bfloat16(v.y - __bfloat162float(h1));
    __nv_bfloat16 l2 = __float2bfloat16(v.z - __bfloat162float(h2));
    __nv_bfloat16 l3 = __float2bfloat16(v.w - __bfloat162float(h3));
    ((__nv_bfloat162*)hi)[2 * i]     = __nv_bfloat162(h0, h1);
    ((__nv_bfloat162*)hi)[2 * i + 1] = __nv_bfloat162(h2, h3);
    ((__nv_bfloat162*)lo)[2 * i]     = __nv_bfloat162(l0, l1);
    ((__nv_bfloat162*)lo)[2 * i + 1] = __nv_bfloat162(l2, l3);
}

// ---------------------------------------------------------------------------
// Retention attention (fp32, unchanged — known good)
// ---------------------------------------------------------------------------
__global__ __launch_bounds__(256) void retention_attn() {
    const int BI = 32, BJ = 32;
    const int QLD = 36;
    __shared__ float Qs[HDIM * QLD];
    __shared__ float KV[HDIM * QLD];
    __shared__ float Ss[BI * BJ];

    int head = blockIdx.y;
    int i0 = blockIdx.x * BI;
    int tid = threadIdx.x;
    int lane = tid & 31;
    int w = tid >> 5;

    const float lg0 = -3.4657359027997265f;
    const float lg1 = -6.2383246250395075f;
    float gamma = 1.0f - expf(lg0 + (lg1 - lg0) * ((float)head * (1.0f / 15.0f)));
    float log2g = log2f(gamma);
    const float scale = 0.088388347648318447f;

    const float* Qh = g_Q + head * HDIM;
    const float* Kh = g_K + head * HDIM;
    const float* Vh = g_V + head * HDIM;

    for (int t = tid; t < BI * HDIM / 4; t += 256) {
        int i = t >> 5;
        int d4 = (t & 31) * 4;
        float4 v = *(const float4*)(Qh + (size_t)(i0 + i) * DIM + d4);
        Qs[(d4 + 0) * QLD + i] = v.x; Qs[(d4 + 1) * QLD + i] = v.y;
        Qs[(d4 + 2) * QLD + i] = v.z; Qs[(d4 + 3) * QLD + i] = v.w;
    }

    float yacc[4][4];
#pragma unroll
    for (int r = 0; r < 4; r++)
#pragma unroll
        for (int q = 0; q < 4; q++) yacc[r][q] = 0.f;

    int nj = blockIdx.x + 1;
    for (int jt = 0; jt < nj; jt++) {
        int j0 = jt * BJ;
        __syncthreads();
        for (int t = tid; t < BJ * HDIM / 4; t += 256) {
            int j = t >> 5;
            int d4 = (t & 31) * 4;
            float4 v = *(const float4*)(Kh + (size_t)(j0 + j) * DIM + d4);
            KV[(d4 + 0) * QLD + j] = v.x; KV[(d4 + 1) * QLD + j] = v.y;
            KV[(d4 + 2) * QLD + j] = v.z; KV[(d4 + 3) * QLD + j] = v.w;
        }
        __syncthreads();

        float sacc[4] = {0.f, 0.f, 0.f, 0.f};
#pragma unroll 4
        for (int d = 0; d < HDIM; d++) {
            float kv = KV[d * QLD + lane];
            float4 qv = *(const float4*)&Qs[d * QLD + w * 4];
            sacc[0] += qv.x * kv;
            sacc[1] += qv.y * kv;
            sacc[2] += qv.z * kv;
            sacc[3] += qv.w * kv;
        }
        int jg = j0 + lane;
#pragma unroll
        for (int r = 0; r < 4; r++) {
            int ig = i0 + w * 4 + r;
            int diff = ig - jg;
            float f = (diff >= 0) ? scale * exp2f(log2g * (float)diff) : 0.0f;
            Ss[(w * 4 + r) * BJ + lane] = sacc[r] * f;
        }
        __syncthreads();

        for (int t = tid; t < BJ * HDIM / 4; t += 256) {
            int j = t >> 5;
            int d4 = (t & 31) * 4;
            float4 v = *(const float4*)(Vh + (size_t)(j0 + j) * DIM + d4);
            *(float4*)&KV[j * HDIM + d4] = v;
        }
        __syncthreads();

#pragma unroll 4
        for (int j = 0; j < BJ; j++) {
            float sv0 = Ss[(w * 4 + 0) * BJ + j];
            float sv1 = Ss[(w * 4 + 1) * BJ + j];
            float sv2 = Ss[(w * 4 + 2) * BJ + j];
            float sv3 = Ss[(w * 4 + 3) * BJ + j];
#pragma unroll
            for (int q = 0; q < 4; q++) {
                float vv = KV[j * HDIM + lane + 32 * q];
                yacc[0][q] += sv0 * vv;
                yacc[1][q] += sv1 * vv;
                yacc[2][q] += sv2 * vv;
                yacc[3][q] += sv3 * vv;
            }
        }
    }

#pragma unroll
    for (int r = 0; r < 4; r++) {
        float* yp = g_Y + (size_t)(i0 + w * 4 + r) * DIM + head * HDIM;
#pragma unroll
        for (int q = 0; q < 4; q++) yp[lane + 32 * q] = yacc[r][q];
    }
}

// ---------------------------------------------------------------------------
// LayerNorm(Y) * silu(G) -> bf16 hi + lo arrays
// ---------------------------------------------------------------------------
__global__ __launch_bounds__(256) void ln_silu_gate(const float* __restrict__ lnw,
                                                    const float* __restrict__ lnb,
                                                    __nv_bfloat16* __restrict__ ohi,
                                                    __nv_bfloat16* __restrict__ olo) {
    int row = blockIdx.x;
    const float* y = g_Y + (size_t)row * DIM;
    const float* g = g_G + (size_t)row * DIM;
    int tid = threadIdx.x;

    float vals[8];
    float s = 0.f, ss = 0.f;
#pragma unroll
    for (int i = 0; i < 2; i++) {
        float4 v = *(const float4*)(y + tid * 4 + i * 1024);
        vals[i * 4 + 0] = v.x; vals[i * 4 + 1] = v.y;
        vals[i * 4 + 2] = v.z; vals[i * 4 + 3] = v.w;
        s += v.x + v.y + v.z + v.w;
        ss += v.x * v.x + v.y * v.y + v.z * v.z + v.w * v.w;
    }
#pragma unroll
    for (int off = 16; off > 0; off >>= 1) {
        s += __shfl_xor_sync(0xFFFFFFFFu, s, off);
        ss += __shfl_xor_sync(0xFFFFFFFFu, ss, off);
    }
    __shared__ float rs[8], rss[8];
    if ((tid & 31) == 0) { rs[tid >> 5] = s; rss[tid >> 5] = ss; }
    __syncthreads();
    s = 0.f; ss = 0.f;
#pragma unroll
    for (int i = 0; i < 8; i++) { s += rs[i]; ss += rss[i]; }

    float mu = s * (1.0f / DIM);
    float var = ss * (1.0f / DIM) - mu * mu;
    float rstd = rsqrtf(var + 1e-5f);

#pragma unroll
    for (int i = 0; i < 2; i++) {
        int c0 = tid * 4 + i * 1024;
        float4 gv = *(const float4*)(g + c0);
        float4 wv = *(const float4*)(lnw + c0);
        float4 bv = *(const float4*)(lnb + c0);
        float o[4];
        o[0] = ((vals[i * 4 + 0] - mu) * rstd * wv.x + bv.x) * (gv.x / (1.0f + expf(-gv.x)));
        o[1] = ((vals[i * 4 + 1] - mu) * rstd * wv.y + bv.y) * (gv.y / (1.0f + expf(-gv.y)));
        o[2] = ((vals[i * 4 + 2] - mu) * rstd * wv.z + bv.z) * (gv.z / (1.0f + expf(-gv.z)));
        o[3] = ((vals[i * 4 + 3] - mu) * rstd * wv.w + bv.w) * (gv.w / (1.0f + expf(-gv.w)));
        __nv_bfloat16 h[4], l[4];
#pragma unroll
        for (int j = 0; j < 4; j++) {
            h[j] = __float2bfloat16(o[j]);
            l[j] = __float2bfloat16(o[j] - __bfloat162float(h[j]));
        }
        size_t base = (size_t)row * DIM + c0;
        *(__nv_bfloat162*)(ohi + base)     = __nv_bfloat162(h[0], h[1]);
        *(__nv_bfloat162*)(ohi + base + 2) = __nv_bfloat162(h[2], h[3]);
        *(__nv_bfloat162*)(olo + base)     = __nv_bfloat162(l[0], l[1]);
        *(__nv_bfloat162*)(olo + base + 2) = __nv_bfloat162(l[2], l[3]);
    }
}

// ---------------------------------------------------------------------------
extern "C" void kernel_launch(void* const* d_in, const int* in_sizes, int n_in,
                              void* d_out, int out_size) {
    const float* x   = (const float*)d_in[0];
    const float* wq  = (const float*)d_in[1];
    const float* wk  = (const float*)d_in[2];
    const float* wv  = (const float*)d_in[3];
    const float* wg  = (const float*)d_in[4];
    const float* wo  = (const float*)d_in[5];
    const float* lnw = (const float*)d_in[6];
    const float* lnb = (const float*)d_in[7];
    float* out = (float*)d_out;

    float *Q, *K, *V, *G;
    __nv_bfloat16 *xhi, *xlo, *ahi, *alo;
    __nv_bfloat16 *whi[5], *wlo[5];
    cudaGetSymbolAddress((void**)&Q, g_Q);
    cudaGetSymbolAddress((void**)&K, g_K);
    cudaGetSymbolAddress((void**)&V, g_V);
    cudaGetSymbolAddress((void**)&G, g_G);
    cudaGetSymbolAddress((void**)&xhi, g_xhi);  cudaGetSymbolAddress((void**)&xlo, g_xlo);
    cudaGetSymbolAddress((void**)&ahi, g_ahi);  cudaGetSymbolAddress((void**)&alo, g_alo);
    cudaGetSymbolAddress((void**)&whi[0], g_wqhi); cudaGetSymbolAddress((void**)&wlo[0], g_wqlo);
    cudaGetSymbolAddress((void**)&whi[1], g_wkhi); cudaGetSymbolAddress((void**)&wlo[1], g_wklo);
    cudaGetSymbolAddress((void**)&whi[2], g_wvhi); cudaGetSymbolAddress((void**)&wlo[2], g_wvlo);
    cudaGetSymbolAddress((void**)&whi[3], g_wghi); cudaGetSymbolAddress((void**)&wlo[3], g_wglo);
    cudaGetSymbolAddress((void**)&whi[4], g_wohi); cudaGetSymbolAddress((void**)&wlo[4], g_wolo);

    cudaFuncSetAttribute(gemm_bf16, cudaFuncAttributeMaxDynamicSharedMemorySize, GEMM_SMEM);

    const int n4 = SEQ * DIM / 4;
    const int cvt_blocks = (n4 + 255) / 256;
    cvt_split<<<cvt_blocks, 256>>>(x,  xhi,    xlo,    n4);
    cvt_split<<<cvt_blocks, 256>>>(wq, whi[0], wlo[0], n4);
    cvt_split<<<cvt_blocks, 256>>>(wk, whi[1], wlo[1], n4);
    cvt_split<<<cvt_blocks, 256>>>(wv, whi[2], wlo[2], n4);
    cvt_split<<<cvt_blocks, 256>>>(wg, whi[3], wlo[3], n4);
    cvt_split<<<cvt_blocks, 256>>>(wo, whi[4], wlo[4], n4);

    dim3 gg(DIM / GBN, SEQ / GBM);  // (16, 16)
    float* proj[4] = {Q, K, V, G};
    for (int p = 0; p < 4; p++) {
        gemm_bf16<<<gg, 256, GEMM_SMEM>>>(xhi, whi[p], proj[p], 0);
        gemm_bf16<<<gg, 256, GEMM_SMEM>>>(xhi, wlo[p], proj[p], 1);
        gemm_bf16<<<gg, 256, GEMM_SMEM>>>(xlo, whi[p], proj[p], 1);
        gemm_bf16<<<gg, 256, GEMM_SMEM>>>(xlo, wlo[p], proj[p], 1);
    }

    retention_attn<<<dim3(SEQ / 32, NH), 256>>>();

    ln_silu_gate<<<SEQ, 256>>>(lnw, lnb, ahi, alo);

    gemm_bf16<<<gg, 256, GEMM_SMEM>>>(ahi, whi[4], out, 0);
    gemm_bf16<<<gg, 256, GEMM_SMEM>>>(ahi, wlo[4], out, 1);
    gemm_bf16<<<gg, 256, GEMM_SMEM>>>(alo, whi[4], out, 1);
    gemm_bf16<<<gg, 256, GEMM_SMEM>>>(alo, wlo[4], out, 1);
}

// round 5
// speedup vs baseline: 3.3241x; 2.5767x over previous
#include <cuda_runtime.h>
#include <cuda_bf16.h>
#include <math.h>
#include <cstdint>

#define SEQ 2048
#define DIM 2048
#define NH 16
#define HDIM 128

// ------------------------- scratch (device globals) -------------------------
__device__ float g_G[SEQ * DIM];
__device__ float g_Y[SEQ * DIM];

__device__ __nv_bfloat16 g_xhi[SEQ * DIM],  g_xlo[SEQ * DIM];
__device__ __nv_bfloat16 g_wqhi[DIM * DIM], g_wqlo[DIM * DIM];
__device__ __nv_bfloat16 g_wkhi[DIM * DIM], g_wklo[DIM * DIM];
__device__ __nv_bfloat16 g_wvhi[DIM * DIM], g_wvlo[DIM * DIM];
__device__ __nv_bfloat16 g_wghi[DIM * DIM], g_wglo[DIM * DIM];
__device__ __nv_bfloat16 g_wohi[DIM * DIM], g_wolo[DIM * DIM];
__device__ __nv_bfloat16 g_Qhi[SEQ * DIM],  g_Qlo[SEQ * DIM];
__device__ __nv_bfloat16 g_Khi[SEQ * DIM],  g_Klo[SEQ * DIM];
__device__ __nv_bfloat16 g_Vhi[SEQ * DIM],  g_Vlo[SEQ * DIM];
__device__ __nv_bfloat16 g_ahi[SEQ * DIM],  g_alo[SEQ * DIM];

// ------------------------- helpers -------------------------
__device__ __forceinline__ uint32_t smem_u32(const void* p) {
    uint32_t a;
    asm("{ .reg .u64 t; cvta.to.shared.u64 t, %1; cvt.u32.u64 %0, t; }" : "=r"(a) : "l"(p));
    return a;
}
__device__ __forceinline__ void cp16(uint32_t dst, const void* src) {
    asm volatile("cp.async.cg.shared.global [%0], [%1], 16;" :: "r"(dst), "l"(src));
}
__device__ __forceinline__ void ldx4(uint32_t* r, uint32_t addr) {
    asm volatile("ldmatrix.sync.aligned.m8n8.x4.shared.b16 {%0,%1,%2,%3}, [%4];"
                 : "=r"(r[0]), "=r"(r[1]), "=r"(r[2]), "=r"(r[3]) : "r"(addr));
}
__device__ __forceinline__ void ldx4t(uint32_t* r, uint32_t addr) {
    asm volatile("ldmatrix.sync.aligned.m8n8.x4.trans.shared.b16 {%0,%1,%2,%3}, [%4];"
                 : "=r"(r[0]), "=r"(r[1]), "=r"(r[2]), "=r"(r[3]) : "r"(addr));
}
__device__ __forceinline__ void mma16816(float* c, const uint32_t* a, uint32_t b0, uint32_t b1) {
    asm volatile(
        "mma.sync.aligned.m16n8k16.row.col.f32.bf16.bf16.f32 "
        "{%0,%1,%2,%3}, {%4,%5,%6,%7}, {%8,%9}, {%0,%1,%2,%3};"
        : "+f"(c[0]), "+f"(c[1]), "+f"(c[2]), "+f"(c[3])
        : "r"(a[0]), "r"(a[1]), "r"(a[2]), "r"(a[3]), "r"(b0), "r"(b1));
}

// ---------------------------------------------------------------------------
// Fused 3-pass hi/lo bf16 GEMM (TN): C = Ahi.Bhi^T + Ahi.Blo^T + Alo.Bhi^T
// M=N=K=2048. Tile 128x128, BK=64, 8 warps (2x4), warp 64x32.
// All four operand tiles of a K-chunk resident in smem; double-buffered.
// mode 0: write fp32 C.  mode 1: write bf16 hi/lo pair (Chi, Clo).
// ---------------------------------------------------------------------------
static constexpr int GBM = 128, GBN = 128, GBK = 64;
static constexpr int NCH = DIM / GBK;         // 32
static constexpr int TILE16K = 16384;         // one 128x64 bf16 tile
static constexpr int GBUF = 4 * TILE16K;      // Ahi|Alo|Bhi|Blo = 64 KB
static constexpr int GEMM_SMEM = 2 * GBUF;    // 128 KB

__device__ __forceinline__ void load_chunk3(uint32_t buf,
                                            const __nv_bfloat16* __restrict__ Ahi,
                                            const __nv_bfloat16* __restrict__ Alo,
                                            const __nv_bfloat16* __restrict__ Bhi,
                                            const __nv_bfloat16* __restrict__ Blo,
                                            int m0, int n0, int kc, int tid) {
    const __nv_bfloat16* srcs[4] = {Ahi, Alo, Bhi, Blo};
#pragma unroll
    for (int it = 0; it < 16; it++) {
        int idx = tid + it * 256;
        int arr = idx >> 10;
        int r = (idx >> 3) & 127;
        int c = idx & 7;
        int grow = (arr < 2 ? m0 : n0) + r;
        uint32_t dst = buf + arr * TILE16K + r * 128 + (((c ^ (r & 7))) << 4);
        cp16(dst, srcs[arr] + (size_t)grow * DIM + kc + c * 8);
    }
}

__global__ __launch_bounds__(256, 1) void gemm3(const __nv_bfloat16* __restrict__ Ahi,
                                                const __nv_bfloat16* __restrict__ Alo,
                                                const __nv_bfloat16* __restrict__ Bhi,
                                                const __nv_bfloat16* __restrict__ Blo,
                                                float* __restrict__ C,
                                                __nv_bfloat16* __restrict__ Chi,
                                                __nv_bfloat16* __restrict__ Clo,
                                                int mode) {
    extern __shared__ char smem[];
    uint32_t sb = smem_u32(smem);
    int tid = threadIdx.x;
    int wid = tid >> 5, lane = tid & 31;
    int wm = wid & 1, wn = wid >> 1;
    int m0 = blockIdx.y * GBM, n0 = blockIdx.x * GBN;

    int a_mh = (lane >> 3) & 1, a_kh = lane >> 4, lr = lane & 7;
    uint32_t aOff[4]; int aR7[4];
#pragma unroll
    for (int i = 0; i < 4; i++) {
        int row = wm * 64 + i * 16 + a_mh * 8 + lr;
        aOff[i] = row * 128; aR7[i] = row & 7;
    }
    int b_jl = lane >> 4, b_kh = (lane >> 3) & 1;
    uint32_t bOff[2]; int bR7[2];
#pragma unroll
    for (int p = 0; p < 2; p++) {
        int row = wn * 32 + p * 16 + b_jl * 8 + lr;
        bOff[p] = row * 128; bR7[p] = row & 7;
    }

    float acc[4][4][4];
#pragma unroll
    for (int i = 0; i < 4; i++)
#pragma unroll
        for (int j = 0; j < 4; j++)
#pragma unroll
            for (int q = 0; q < 4; q++) acc[i][j][q] = 0.f;

    load_chunk3(sb, Ahi, Alo, Bhi, Blo, m0, n0, 0, tid);
    asm volatile("cp.async.commit_group;" ::: "memory");

    for (int t = 0; t < NCH; t++) {
        if (t + 1 < NCH) {
            load_chunk3(sb + ((t + 1) & 1) * GBUF, Ahi, Alo, Bhi, Blo, m0, n0, (t + 1) * GBK, tid);
            asm volatile("cp.async.commit_group;" ::: "memory");
            asm volatile("cp.async.wait_group 1;" ::: "memory");
        } else {
            asm volatile("cp.async.wait_group 0;" ::: "memory");
        }
        __syncthreads();

        uint32_t bufAh = sb + (t & 1) * GBUF;
        uint32_t bufAl = bufAh + TILE16K;
        uint32_t bufBh = bufAh + 2 * TILE16K;
        uint32_t bufBl = bufAh + 3 * TILE16K;
#pragma unroll
        for (int ks = 0; ks < 4; ks++) {
            int ca = ks * 2 + a_kh;
            int cb = ks * 2 + b_kh;
            uint32_t ah[4][4], bh[2][4], bl[2][4];
#pragma unroll
            for (int i = 0; i < 4; i++)
                ldx4(ah[i], bufAh + aOff[i] + (((uint32_t)(ca ^ aR7[i])) << 4));
#pragma unroll
            for (int p = 0; p < 2; p++) {
                ldx4(bh[p], bufBh + bOff[p] + (((uint32_t)(cb ^ bR7[p])) << 4));
                ldx4(bl[p], bufBl + bOff[p] + (((uint32_t)(cb ^ bR7[p])) << 4));
            }
#pragma unroll
            for (int i = 0; i < 4; i++)
#pragma unroll
                for (int j = 0; j < 4; j++) {
                    int p = j >> 1, jl = j & 1;
                    mma16816(acc[i][j], ah[i], bh[p][2 * jl], bh[p][2 * jl + 1]);
                    mma16816(acc[i][j], ah[i], bl[p][2 * jl], bl[p][2 * jl + 1]);
                }
            uint32_t al[4][4];
#pragma unroll
            for (int i = 0; i < 4; i++)
                ldx4(al[i], bufAl + aOff[i] + (((uint32_t)(ca ^ aR7[i])) << 4));
#pragma unroll
            for (int i = 0; i < 4; i++)
#pragma unroll
                for (int j = 0; j < 4; j++) {
                    int p = j >> 1, jl = j & 1;
                    mma16816(acc[i][j], al[i], bh[p][2 * jl], bh[p][2 * jl + 1]);
                }
        }
        __syncthreads();
    }

    int qr = lane >> 2, qc = (lane & 3) * 2;
#pragma unroll
    for (int i = 0; i < 4; i++) {
        int mrow = m0 + wm * 64 + i * 16 + qr;
#pragma unroll
        for (int j = 0; j < 4; j++) {
            size_t base = (size_t)mrow * DIM + n0 + wn * 32 + j * 8 + qc;
            if (mode == 0) {
                C[base]               = acc[i][j][0];
                C[base + 1]           = acc[i][j][1];
                C[base + 8 * DIM]     = acc[i][j][2];
                C[base + 8 * DIM + 1] = acc[i][j][3];
            } else {
#pragma unroll
                for (int h2 = 0; h2 < 2; h2++) {
                    float v0 = acc[i][j][h2 * 2], v1 = acc[i][j][h2 * 2 + 1];
                    __nv_bfloat16 h0 = __float2bfloat16(v0), h1 = __float2bfloat16(v1);
                    __nv_bfloat16 l0 = __float2bfloat16(v0 - __bfloat162float(h0));
                    __nv_bfloat16 l1 = __float2bfloat16(v1 - __bfloat162float(h1));
                    size_t bb = base + h2 * 8 * DIM;
                    *(__nv_bfloat162*)(Chi + bb) = __nv_bfloat162(h0, h1);
                    *(__nv_bfloat162*)(Clo + bb) = __nv_bfloat162(l0, l1);
                }
            }
        }
    }
}

// ---------------------------------------------------------------------------
// fp32 -> separate bf16 hi / lo arrays
// ---------------------------------------------------------------------------
__global__ __launch_bounds__(256) void cvt_split(const float* __restrict__ s,
                                                 __nv_bfloat16* __restrict__ hi,
                                                 __nv_bfloat16* __restrict__ lo, int n4) {
    int i = blockIdx.x * 256 + threadIdx.x;
    if (i >= n4) return;
    float4 v = ((const float4*)s)[i];
    __nv_bfloat16 h0 = __float2bfloat16(v.x), h1 = __float2bfloat16(v.y);
    __nv_bfloat16 h2 = __float2bfloat16(v.z), h3 = __float2bfloat16(v.w);
    __nv_bfloat16 l0 = __float2bfloat16(v.x - __bfloat162float(h0));
    __nv_bfloat16 l1 = __float2bfloat16(v.y - __bfloat162float(h1));
    __nv_bfloat16 l2 = __float2bfloat16(v.z - __bfloat162float(h2));
    __nv_bfloat16 l3 = __float2bfloat16(v.w - __bfloat162float(h3));
    ((__nv_bfloat162*)hi)[2 * i]     = __nv_bfloat162(h0, h1);
    ((__nv_bfloat162*)hi)[2 * i + 1] = __nv_bfloat162(h2, h3);
    ((__nv_bfloat162*)lo)[2 * i]     = __nv_bfloat162(l0, l1);
    ((__nv_bfloat162*)lo)[2 * i + 1] = __nv_bfloat162(l2, l3);
}

// ---------------------------------------------------------------------------
// Tensor-core retention attention.
// grid (32 i-tiles, 16 heads), 256 threads (8 warps, 2x4).
// BI=BJ=64. Stage1: S = Q.K^T hi/lo 3-pass -> decay (factorized exp2) ->
// bf16 hi/lo in smem. Stage2: Y += S.V hi/lo 3-pass (V B-frags via ldmatrix.trans).
// ---------------------------------------------------------------------------
static constexpr int AT_SMEM = 112 * 1024;

__global__ __launch_bounds__(256, 1) void retention_tc() {
    extern __shared__ char smem[];
    uint32_t sb = smem_u32(smem);
    const uint32_t Qh_s = sb;
    const uint32_t Ql_s = sb + 16384;
    const uint32_t Kh_s = sb + 32768;
    const uint32_t Kl_s = sb + 49152;
    const uint32_t Vh_s = sb + 65536;
    const uint32_t Vl_s = sb + 81920;
    const uint32_t Sh_s = sb + 98304;
    const uint32_t Sl_s = sb + 106496;

    int head = blockIdx.y;
    int it = gridDim.x - 1 - blockIdx.x;   // heaviest blocks first
    int i0 = it * 64;
    int tid = threadIdx.x, lane = tid & 31, wid = tid >> 5;
    int wm = wid & 1, wn = wid >> 1;

    const float lg0 = -3.4657359027997265f;
    const float lg1 = -6.2383246250395075f;
    float gamma = 1.0f - expf(lg0 + (lg1 - lg0) * ((float)head * (1.0f / 15.0f)));
    float log2g = log2f(gamma);
    const float scale = 0.088388347648318447f;

    const __nv_bfloat16* Qhg = g_Qhi + head * HDIM;
    const __nv_bfloat16* Qlg = g_Qlo + head * HDIM;
    const __nv_bfloat16* Khg = g_Khi + head * HDIM;
    const __nv_bfloat16* Klg = g_Klo + head * HDIM;
    const __nv_bfloat16* Vhg = g_Vhi + head * HDIM;
    const __nv_bfloat16* Vlg = g_Vlo + head * HDIM;

    int qr = lane >> 2, qc = (lane & 3) * 2;
    int a_mh = (lane >> 3) & 1, a_kh = lane >> 4, lr = lane & 7;
    int b_jl = lane >> 4, b_kh = (lane >> 3) & 1;
    int v_m = (lane >> 3) & 1, v_g = lane >> 4;

    uint32_t aOff[2]; int aR7[2];
#pragma unroll
    for (int i = 0; i < 2; i++) {
        int row = wm * 32 + i * 16 + a_mh * 8 + lr;
        aOff[i] = row * 128; aR7[i] = row & 7;
    }
    int brow = wn * 16 + b_jl * 8 + lr;
    uint32_t bOff = brow * 128; int bR7 = brow & 7;

    float colfac[2][2];
#pragma unroll
    for (int jf = 0; jf < 2; jf++)
#pragma unroll
        for (int lb = 0; lb < 2; lb++) {
            int dj = wn * 16 + jf * 8 + qc + lb;
            colfac[jf][lb] = exp2f(-log2g * (float)dj) * scale;
        }

    // stage Q (hi+lo, 2 chunk-tiles) — completes with first K/V wait
#pragma unroll
    for (int l = 0; l < 8; l++) {
        int idx = tid + l * 256;
        int arr = idx >> 10, ct = (idx >> 9) & 1, r = (idx >> 3) & 63, c = idx & 7;
        const __nv_bfloat16* src = (arr ? Qlg : Qhg) + (size_t)(i0 + r) * DIM + ct * 64 + c * 8;
        uint32_t dst = (arr ? Ql_s : Qh_s) + ct * 8192 + r * 128 + (((c ^ (r & 7))) << 4);
        cp16(dst, src);
    }

    float yacc[2][4][4];
#pragma unroll
    for (int i = 0; i < 2; i++)
#pragma unroll
        for (int t = 0; t < 4; t++)
#pragma unroll
            for (int q = 0; q < 4; q++) yacc[i][t][q] = 0.f;

    for (int jt = 0; jt <= it; jt++) {
        int j0 = jt * 64;
        if (jt > 0) __syncthreads();   // K/V/S reuse protection

        // load K (hi/lo, chunked like Q) and V (hi/lo, [j][128] 256B rows)
#pragma unroll
        for (int l = 0; l < 8; l++) {
            int idx = tid + l * 256;
            int arr = idx >> 10, ct = (idx >> 9) & 1, r = (idx >> 3) & 63, c = idx & 7;
            const __nv_bfloat16* src = (arr ? Klg : Khg) + (size_t)(j0 + r) * DIM + ct * 64 + c * 8;
            uint32_t dst = (arr ? Kl_s : Kh_s) + ct * 8192 + r * 128 + (((c ^ (r & 7))) << 4);
            cp16(dst, src);
        }
#pragma unroll
        for (int l = 0; l < 8; l++) {
            int idx = tid + l * 256;
            int arr = idx >> 10, r = (idx >> 4) & 63, dc = idx & 15;
            const __nv_bfloat16* src = (arr ? Vlg : Vhg) + (size_t)(j0 + r) * DIM + dc * 8;
            uint32_t dst = (arr ? Vl_s : Vh_s) + r * 256 + (((dc ^ (r & 7))) << 4);
            cp16(dst, src);
        }
        asm volatile("cp.async.commit_group;" ::: "memory");
        asm volatile("cp.async.wait_group 0;" ::: "memory");
        __syncthreads();

        // ---- stage 1: S = Q.K^T (3-pass hi/lo) ----
        float acc1[2][2][4];
#pragma unroll
        for (int i = 0; i < 2; i++)
#pragma unroll
            for (int j = 0; j < 2; j++)
#pragma unroll
                for (int q = 0; q < 4; q++) acc1[i][j][q] = 0.f;

#pragma unroll
        for (int ct = 0; ct < 2; ct++) {
#pragma unroll
            for (int ks = 0; ks < 4; ks++) {
                int ca = ks * 2 + a_kh;
                int cb = ks * 2 + b_kh;
                uint32_t qh[2][4], ql[2][4], bh[4], bl[4];
#pragma unroll
                for (int i = 0; i < 2; i++) {
                    ldx4(qh[i], Qh_s + ct * 8192 + aOff[i] + (((uint32_t)(ca ^ aR7[i])) << 4));
                    ldx4(ql[i], Ql_s + ct * 8192 + aOff[i] + (((uint32_t)(ca ^ aR7[i])) << 4));
                }
                ldx4(bh, Kh_s + ct * 8192 + bOff + (((uint32_t)(cb ^ bR7)) << 4));
                ldx4(bl, Kl_s + ct * 8192 + bOff + (((uint32_t)(cb ^ bR7)) << 4));
#pragma unroll
                for (int i = 0; i < 2; i++)
#pragma unroll
                    for (int j = 0; j < 2; j++) {
                        mma16816(acc1[i][j], qh[i], bh[2 * j], bh[2 * j + 1]);
                        mma16816(acc1[i][j], qh[i], bl[2 * j], bl[2 * j + 1]);
                        mma16816(acc1[i][j], ql[i], bh[2 * j], bh[2 * j + 1]);
                    }
            }
        }

        // ---- decay, mask, split -> Ss ----
        float rowfac[2][2];
#pragma unroll
        for (int i = 0; i < 2; i++)
#pragma unroll
            for (int h = 0; h < 2; h++) {
                int rrel = i0 - j0 + wm * 32 + i * 16 + qr + h * 8;
                rowfac[i][h] = exp2f(log2g * (float)rrel);
            }
#pragma unroll
        for (int i = 0; i < 2; i++)
#pragma unroll
            for (int j = 0; j < 2; j++)
#pragma unroll
                for (int h = 0; h < 2; h++) {
                    int row = wm * 32 + i * 16 + qr + h * 8;
                    int col = wn * 16 + j * 8 + qc;
                    int diff0 = (i0 + row) - (j0 + col);
                    float v0 = (diff0 >= 0) ? acc1[i][j][h * 2 + 0] * rowfac[i][h] * colfac[j][0] : 0.f;
                    float v1 = (diff0 >= 1) ? acc1[i][j][h * 2 + 1] * rowfac[i][h] * colfac[j][1] : 0.f;
                    __nv_bfloat16 h0 = __float2bfloat16(v0), h1 = __float2bfloat16(v1);
                    __nv_bfloat16 l0 = __float2bfloat16(v0 - __bfloat162float(h0));
                    __nv_bfloat16 l1 = __float2bfloat16(v1 - __bfloat162float(h1));
                    uint32_t off = row * 128 + ((((col >> 3) ^ (row & 7))) << 4) + (col & 7) * 2;
                    *(__nv_bfloat162*)(smem + (Sh_s - sb) + off) = __nv_bfloat162(h0, h1);
                    *(__nv_bfloat162*)(smem + (Sl_s - sb) + off) = __nv_bfloat162(l0, l1);
                }
        __syncthreads();

        // ---- stage 2: Y += S.V (3-pass hi/lo) ----
#pragma unroll
        for (int ks = 0; ks < 4; ks++) {
            int ca = ks * 2 + a_kh;
            uint32_t sh[2][4], sl[2][4], vh[2][4], vl[2][4];
#pragma unroll
            for (int i = 0; i < 2; i++) {
                ldx4(sh[i], Sh_s + aOff[i] + (((uint32_t)(ca ^ aR7[i])) << 4));
                ldx4(sl[i], Sl_s + aOff[i] + (((uint32_t)(ca ^ aR7[i])) << 4));
            }
            int vrow = ks * 16 + v_m * 8 + lr;
#pragma unroll
            for (int g = 0; g < 2; g++) {
                int dc = wn * 4 + g * 2 + v_g;
                uint32_t vo = vrow * 256 + (((uint32_t)(dc ^ (vrow & 7))) << 4);
                ldx4t(vh[g], Vh_s + vo);
                ldx4t(vl[g], Vl_s + vo);
            }
#pragma unroll
            for (int i = 0; i < 2; i++)
#pragma unroll
                for (int t = 0; t < 4; t++) {
                    int g = t >> 1, s2 = (t & 1) * 2;
                    mma16816(yacc[i][t], sh[i], vh[g][s2], vh[g][s2 + 1]);
                    mma16816(yacc[i][t], sh[i], vl[g][s2], vl[g][s2 + 1]);
                    mma16816(yacc[i][t], sl[i], vh[g][s2], vh[g][s2 + 1]);
                }
        }
    }

    // epilogue -> g_Y fp32
#pragma unroll
    for (int i = 0; i < 2; i++) {
        int row = i0 + wm * 32 + i * 16 + qr;
#pragma unroll
        for (int t = 0; t < 4; t++) {
            float* yp = g_Y + (size_t)row * DIM + head * HDIM + wn * 32 + t * 8 + qc;
            *(float2*)yp = make_float2(yacc[i][t][0], yacc[i][t][1]);
            *(float2*)(yp + 8 * DIM) = make_float2(yacc[i][t][2], yacc[i][t][3]);
        }
    }
}

// ---------------------------------------------------------------------------
// LayerNorm(Y) * silu(G) -> bf16 hi + lo arrays
// ---------------------------------------------------------------------------
__global__ __launch_bounds__(256) void ln_silu_gate(const float* __restrict__ lnw,
                                                    const float* __restrict__ lnb,
                                                    __nv_bfloat16* __restrict__ ohi,
                                                    __nv_bfloat16* __restrict__ olo) {
    int row = blockIdx.x;
    const float* y = g_Y + (size_t)row * DIM;
    const float* g = g_G + (size_t)row * DIM;
    int tid = threadIdx.x;

    float vals[8];
    float s = 0.f, ss = 0.f;
#pragma unroll
    for (int i = 0; i < 2; i++) {
        float4 v = *(const float4*)(y + tid * 4 + i * 1024);
        vals[i * 4 + 0] = v.x; vals[i * 4 + 1] = v.y;
        vals[i * 4 + 2] = v.z; vals[i * 4 + 3] = v.w;
        s += v.x + v.y + v.z + v.w;
        ss += v.x * v.x + v.y * v.y + v.z * v.z + v.w * v.w;
    }
#pragma unroll
    for (int off = 16; off > 0; off >>= 1) {
        s += __shfl_xor_sync(0xFFFFFFFFu, s, off);
        ss += __shfl_xor_sync(0xFFFFFFFFu, ss, off);
    }
    __shared__ float rs[8], rss[8];
    if ((tid & 31) == 0) { rs[tid >> 5] = s; rss[tid >> 5] = ss; }
    __syncthreads();
    s = 0.f; ss = 0.f;
#pragma unroll
    for (int i = 0; i < 8; i++) { s += rs[i]; ss += rss[i]; }

    float mu = s * (1.0f / DIM);
    float var = ss * (1.0f / DIM) - mu * mu;
    float rstd = rsqrtf(var + 1e-5f);

#pragma unroll
    for (int i = 0; i < 2; i++) {
        int c0 = tid * 4 + i * 1024;
        float4 gv = *(const float4*)(g + c0);
        float4 wv = *(const float4*)(lnw + c0);
        float4 bv = *(const float4*)(lnb + c0);
        float o[4];
        o[0] = ((vals[i * 4 + 0] - mu) * rstd * wv.x + bv.x) * (gv.x / (1.0f + expf(-gv.x)));
        o[1] = ((vals[i * 4 + 1] - mu) * rstd * wv.y + bv.y) * (gv.y / (1.0f + expf(-gv.y)));
        o[2] = ((vals[i * 4 + 2] - mu) * rstd * wv.z + bv.z) * (gv.z / (1.0f + expf(-gv.z)));
        o[3] = ((vals[i * 4 + 3] - mu) * rstd * wv.w + bv.w) * (gv.w / (1.0f + expf(-gv.w)));
        __nv_bfloat16 h[4], l[4];
#pragma unroll
        for (int j = 0; j < 4; j++) {
            h[j] = __float2bfloat16(o[j]);
            l[j] = __float2bfloat16(o[j] - __bfloat162float(h[j]));
        }
        size_t base = (size_t)row * DIM + c0;
        *(__nv_bfloat162*)(ohi + base)     = __nv_bfloat162(h[0], h[1]);
        *(__nv_bfloat162*)(ohi + base + 2) = __nv_bfloat162(h[2], h[3]);
        *(__nv_bfloat162*)(olo + base)     = __nv_bfloat162(l[0], l[1]);
        *(__nv_bfloat162*)(olo + base + 2) = __nv_bfloat162(l[2], l[3]);
    }
}

// ---------------------------------------------------------------------------
extern "C" void kernel_launch(void* const* d_in, const int* in_sizes, int n_in,
                              void* d_out, int out_size) {
    const float* x   = (const float*)d_in[0];
    const float* wq  = (const float*)d_in[1];
    const float* wk  = (const float*)d_in[2];
    const float* wv  = (const float*)d_in[3];
    const float* wg  = (const float*)d_in[4];
    const float* wo  = (const float*)d_in[5];
    const float* lnw = (const float*)d_in[6];
    const float* lnb = (const float*)d_in[7];
    float* out = (float*)d_out;

    float *G, *Y;
    __nv_bfloat16 *xhi, *xlo, *ahi, *alo;
    __nv_bfloat16 *whi[5], *wlo[5];
    __nv_bfloat16 *qhi, *qlo, *khi, *klo, *vhi, *vlo;
    cudaGetSymbolAddress((void**)&G, g_G);
    cudaGetSymbolAddress((void**)&Y, g_Y);
    cudaGetSymbolAddress((void**)&xhi, g_xhi);  cudaGetSymbolAddress((void**)&xlo, g_xlo);
    cudaGetSymbolAddress((void**)&ahi, g_ahi);  cudaGetSymbolAddress((void**)&alo, g_alo);
    cudaGetSymbolAddress((void**)&whi[0], g_wqhi); cudaGetSymbolAddress((void**)&wlo[0], g_wqlo);
    cudaGetSymbolAddress((void**)&whi[1], g_wkhi); cudaGetSymbolAddress((void**)&wlo[1], g_wklo);
    cudaGetSymbolAddress((void**)&whi[2], g_wvhi); cudaGetSymbolAddress((void**)&wlo[2], g_wvlo);
    cudaGetSymbolAddress((void**)&whi[3], g_wghi); cudaGetSymbolAddress((void**)&wlo[3], g_wglo);
    cudaGetSymbolAddress((void**)&whi[4], g_wohi); cudaGetSymbolAddress((void**)&wlo[4], g_wolo);
    cudaGetSymbolAddress((void**)&qhi, g_Qhi); cudaGetSymbolAddress((void**)&qlo, g_Qlo);
    cudaGetSymbolAddress((void**)&khi, g_Khi); cudaGetSymbolAddress((void**)&klo, g_Klo);
    cudaGetSymbolAddress((void**)&vhi, g_Vhi); cudaGetSymbolAddress((void**)&vlo, g_Vlo);

    cudaFuncSetAttribute(gemm3, cudaFuncAttributeMaxDynamicSharedMemorySize, GEMM_SMEM);
    cudaFuncSetAttribute(retention_tc, cudaFuncAttributeMaxDynamicSharedMemorySize, AT_SMEM);

    const int n4 = SEQ * DIM / 4;
    const int cvt_blocks = (n4 + 255) / 256;
    cvt_split<<<cvt_blocks, 256>>>(x,  xhi,    xlo,    n4);
    cvt_split<<<cvt_blocks, 256>>>(wq, whi[0], wlo[0], n4);
    cvt_split<<<cvt_blocks, 256>>>(wk, whi[1], wlo[1], n4);
    cvt_split<<<cvt_blocks, 256>>>(wv, whi[2], wlo[2], n4);
    cvt_split<<<cvt_blocks, 256>>>(wg, whi[3], wlo[3], n4);
    cvt_split<<<cvt_blocks, 256>>>(wo, whi[4], wlo[4], n4);

    dim3 gg(DIM / GBN, SEQ / GBM);  // (16, 16)
    gemm3<<<gg, 256, GEMM_SMEM>>>(xhi, xlo, whi[0], wlo[0], nullptr, qhi, qlo, 1);
    gemm3<<<gg, 256, GEMM_SMEM>>>(xhi, xlo, whi[1], wlo[1], nullptr, khi, klo, 1);
    gemm3<<<gg, 256, GEMM_SMEM>>>(xhi, xlo, whi[2], wlo[2], nullptr, vhi, vlo, 1);
    gemm3<<<gg, 256, GEMM_SMEM>>>(xhi, xlo, whi[3], wlo[3], G, nullptr, nullptr, 0);

    retention_tc<<<dim3(SEQ / 64, NH), 256, AT_SMEM>>>();

    ln_silu_gate<<<SEQ, 256>>>(lnw, lnb, ahi, alo);

    gemm3<<<gg, 256, GEMM_SMEM>>>(ahi, alo, whi[4], wlo[4], out, nullptr, nullptr, 0);
}

// round 6
// speedup vs baseline: 3.5639x; 1.0721x over previous
#include <cuda_runtime.h>
#include <cuda_bf16.h>
#include <math.h>
#include <cstdint>

#define SEQ 2048
#define DIM 2048
#define NH 16
#define HDIM 128

// ------------------------- scratch (device globals) -------------------------
__device__ float g_G[SEQ * DIM];
__device__ float g_Y[SEQ * DIM];

__device__ __nv_bfloat16 g_xhi[SEQ * DIM],  g_xlo[SEQ * DIM];
__device__ __nv_bfloat16 g_wqhi[DIM * DIM], g_wqlo[DIM * DIM];
__device__ __nv_bfloat16 g_wkhi[DIM * DIM], g_wklo[DIM * DIM];
__device__ __nv_bfloat16 g_wvhi[DIM * DIM], g_wvlo[DIM * DIM];
__device__ __nv_bfloat16 g_wghi[DIM * DIM], g_wglo[DIM * DIM];
__device__ __nv_bfloat16 g_wohi[DIM * DIM], g_wolo[DIM * DIM];
__device__ __nv_bfloat16 g_Qhi[SEQ * DIM],  g_Qlo[SEQ * DIM];
__device__ __nv_bfloat16 g_Khi[SEQ * DIM],  g_Klo[SEQ * DIM];
__device__ __nv_bfloat16 g_Vhi[SEQ * DIM],  g_Vlo[SEQ * DIM];
__device__ __nv_bfloat16 g_ahi[SEQ * DIM],  g_alo[SEQ * DIM];

// ------------------------- helpers -------------------------
__device__ __forceinline__ uint32_t smem_u32(const void* p) {
    uint32_t a;
    asm("{ .reg .u64 t; cvta.to.shared.u64 t, %1; cvt.u32.u64 %0, t; }" : "=r"(a) : "l"(p));
    return a;
}
__device__ __forceinline__ void cp16(uint32_t dst, const void* src) {
    asm volatile("cp.async.cg.shared.global [%0], [%1], 16;" :: "r"(dst), "l"(src));
}
__device__ __forceinline__ void ldx4(uint32_t* r, uint32_t addr) {
    asm volatile("ldmatrix.sync.aligned.m8n8.x4.shared.b16 {%0,%1,%2,%3}, [%4];"
                 : "=r"(r[0]), "=r"(r[1]), "=r"(r[2]), "=r"(r[3]) : "r"(addr));
}
__device__ __forceinline__ void ldx4t(uint32_t* r, uint32_t addr) {
    asm volatile("ldmatrix.sync.aligned.m8n8.x4.trans.shared.b16 {%0,%1,%2,%3}, [%4];"
                 : "=r"(r[0]), "=r"(r[1]), "=r"(r[2]), "=r"(r[3]) : "r"(addr));
}
__device__ __forceinline__ void mma16816(float* c, const uint32_t* a, uint32_t b0, uint32_t b1) {
    asm volatile(
        "mma.sync.aligned.m16n8k16.row.col.f32.bf16.bf16.f32 "
        "{%0,%1,%2,%3}, {%4,%5,%6,%7}, {%8,%9}, {%0,%1,%2,%3};"
        : "+f"(c[0]), "+f"(c[1]), "+f"(c[2]), "+f"(c[3])
        : "r"(a[0]), "r"(a[1]), "r"(a[2]), "r"(a[3]), "r"(b0), "r"(b1));
}

// ---------------------------------------------------------------------------
// Fused 3-pass hi/lo bf16 GEMM (TN): C = Ahi.Bhi^T + Ahi.Blo^T + Alo.Bhi^T
// M=K=2048, tile 128(M) x 256(N), BK=64. 8 warps (2x4), warp 64x64.
// Single-wave grid (8 x 16 = 128 CTAs). Double-buffered cp.async.
// mode 0: write fp32 C.  mode 1: write bf16 hi/lo pair (Chi, Clo).
// ---------------------------------------------------------------------------
static constexpr int GBM = 128, GBN = 256, GBK = 64;
static constexpr int NCH = DIM / GBK;       // 32
static constexpr int OF_AH = 0;
static constexpr int OF_AL = 16384;
static constexpr int OF_BH = 32768;
static constexpr int OF_BL = 65536;
static constexpr int GBUF = 98304;          // 96 KB per stage
static constexpr int GEMM_SMEM = 2 * GBUF;  // 192 KB

__device__ __forceinline__ void load_chunk3(uint32_t buf,
                                            const __nv_bfloat16* __restrict__ Ahi,
                                            const __nv_bfloat16* __restrict__ Alo,
                                            const __nv_bfloat16* __restrict__ Bhi,
                                            const __nv_bfloat16* __restrict__ Blo,
                                            int m0, int n0, int kc, int tid) {
#pragma unroll
    for (int it = 0; it < 24; it++) {
        int idx = tid + it * 256;          // 0..6143
        int r = idx >> 3, c = idx & 7;     // r: 0..767 global row slot
        const __nv_bfloat16* src;
        uint32_t base;
        int rr, grow;
        if (r < 256) {                     // A tiles (128 rows each)
            rr = r & 127;
            src = (r < 128) ? Ahi : Alo;
            base = buf + ((r < 128) ? OF_AH : OF_AL);
            grow = m0 + rr;
        } else {                           // B tiles (256 rows each)
            rr = (r - 256) & 255;
            src = (r < 512) ? Bhi : Blo;
            base = buf + ((r < 512) ? OF_BH : OF_BL);
            grow = n0 + rr;
        }
        uint32_t dst = base + rr * 128 + (((c ^ (rr & 7))) << 4);
        cp16(dst, src + (size_t)grow * DIM + kc + c * 8);
    }
}

__global__ __launch_bounds__(256, 1) void gemm3(const __nv_bfloat16* __restrict__ Ahi,
                                                const __nv_bfloat16* __restrict__ Alo,
                                                const __nv_bfloat16* __restrict__ Bhi,
                                                const __nv_bfloat16* __restrict__ Blo,
                                                float* __restrict__ C,
                                                __nv_bfloat16* __restrict__ Chi,
                                                __nv_bfloat16* __restrict__ Clo,
                                                int mode) {
    extern __shared__ char smem[];
    uint32_t sb = smem_u32(smem);
    int tid = threadIdx.x;
    int wid = tid >> 5, lane = tid & 31;
    int wm = wid & 1, wn = wid >> 1;          // 2 x 4 warps; warp tile 64M x 64N
    int m0 = blockIdx.y * GBM, n0 = blockIdx.x * GBN;

    int a_mh = (lane >> 3) & 1, a_kh = lane >> 4, lr = lane & 7;
    uint32_t aOff[4]; int aR7[4];
#pragma unroll
    for (int i = 0; i < 4; i++) {
        int row = wm * 64 + i * 16 + a_mh * 8 + lr;
        aOff[i] = row * 128; aR7[i] = row & 7;
    }
    int b_jl = lane >> 4, b_kh = (lane >> 3) & 1;
    uint32_t bOff[4]; int bR7[4];
#pragma unroll
    for (int p = 0; p < 4; p++) {
        int row = wn * 64 + p * 16 + b_jl * 8 + lr;
        bOff[p] = row * 128; bR7[p] = row & 7;
    }

    float acc[4][8][4];
#pragma unroll
    for (int i = 0; i < 4; i++)
#pragma unroll
        for (int j = 0; j < 8; j++)
#pragma unroll
            for (int q = 0; q < 4; q++) acc[i][j][q] = 0.f;

    load_chunk3(sb, Ahi, Alo, Bhi, Blo, m0, n0, 0, tid);
    asm volatile("cp.async.commit_group;" ::: "memory");

    for (int t = 0; t < NCH; t++) {
        if (t + 1 < NCH) {
            load_chunk3(sb + ((t + 1) & 1) * GBUF, Ahi, Alo, Bhi, Blo, m0, n0, (t + 1) * GBK, tid);
            asm volatile("cp.async.commit_group;" ::: "memory");
            asm volatile("cp.async.wait_group 1;" ::: "memory");
        } else {
            asm volatile("cp.async.wait_group 0;" ::: "memory");
        }
        __syncthreads();

        uint32_t buf = sb + (t & 1) * GBUF;
#pragma unroll
        for (int ks = 0; ks < 4; ks++) {
            int ca = ks * 2 + a_kh;
            int cb = ks * 2 + b_kh;
            uint32_t ah[4][4], bh[4][4], bl[4][4];
#pragma unroll
            for (int i = 0; i < 4; i++)
                ldx4(ah[i], buf + OF_AH + aOff[i] + (((uint32_t)(ca ^ aR7[i])) << 4));
#pragma unroll
            for (int p = 0; p < 4; p++) {
                ldx4(bh[p], buf + OF_BH + bOff[p] + (((uint32_t)(cb ^ bR7[p])) << 4));
                ldx4(bl[p], buf + OF_BL + bOff[p] + (((uint32_t)(cb ^ bR7[p])) << 4));
            }
#pragma unroll
            for (int i = 0; i < 4; i++)
#pragma unroll
                for (int j = 0; j < 8; j++) {
                    int p = j >> 1, jl = j & 1;
                    mma16816(acc[i][j], ah[i], bh[p][2 * jl], bh[p][2 * jl + 1]);
                    mma16816(acc[i][j], ah[i], bl[p][2 * jl], bl[p][2 * jl + 1]);
                }
            uint32_t al[4][4];
#pragma unroll
            for (int i = 0; i < 4; i++)
                ldx4(al[i], buf + OF_AL + aOff[i] + (((uint32_t)(ca ^ aR7[i])) << 4));
#pragma unroll
            for (int i = 0; i < 4; i++)
#pragma unroll
                for (int j = 0; j < 8; j++) {
                    int p = j >> 1, jl = j & 1;
                    mma16816(acc[i][j], al[i], bh[p][2 * jl], bh[p][2 * jl + 1]);
                }
        }
        __syncthreads();
    }

    int qr = lane >> 2, qc = (lane & 3) * 2;
#pragma unroll
    for (int i = 0; i < 4; i++) {
        int mrow = m0 + wm * 64 + i * 16 + qr;
#pragma unroll
        for (int j = 0; j < 8; j++) {
            size_t base = (size_t)mrow * DIM + n0 + wn * 64 + j * 8 + qc;
            if (mode == 0) {
                C[base]               = acc[i][j][0];
                C[base + 1]           = acc[i][j][1];
                C[base + 8 * DIM]     = acc[i][j][2];
                C[base + 8 * DIM + 1] = acc[i][j][3];
            } else {
#pragma unroll
                for (int h2 = 0; h2 < 2; h2++) {
                    float v0 = acc[i][j][h2 * 2], v1 = acc[i][j][h2 * 2 + 1];
                    __nv_bfloat16 h0 = __float2bfloat16(v0), h1 = __float2bfloat16(v1);
                    __nv_bfloat16 l0 = __float2bfloat16(v0 - __bfloat162float(h0));
                    __nv_bfloat16 l1 = __float2bfloat16(v1 - __bfloat162float(h1));
                    size_t bb = base + h2 * 8 * DIM;
                    *(__nv_bfloat162*)(Chi + bb) = __nv_bfloat162(h0, h1);
                    *(__nv_bfloat162*)(Clo + bb) = __nv_bfloat162(l0, l1);
                }
            }
        }
    }
}

// ---------------------------------------------------------------------------
// fp32 -> bf16 hi/lo; 4 independent float4 per thread (MLP=4)
// ---------------------------------------------------------------------------
__global__ __launch_bounds__(256) void cvt_split(const float* __restrict__ s,
                                                 __nv_bfloat16* __restrict__ hi,
                                                 __nv_bfloat16* __restrict__ lo) {
    int base = blockIdx.x * 1024 + threadIdx.x;
    float4 v[4];
#pragma unroll
    for (int u = 0; u < 4; u++) v[u] = ((const float4*)s)[base + u * 256];
#pragma unroll
    for (int u = 0; u < 4; u++) {
        int i = base + u * 256;
        __nv_bfloat16 h0 = __float2bfloat16(v[u].x), h1 = __float2bfloat16(v[u].y);
        __nv_bfloat16 h2 = __float2bfloat16(v[u].z), h3 = __float2bfloat16(v[u].w);
        __nv_bfloat16 l0 = __float2bfloat16(v[u].x - __bfloat162float(h0));
        __nv_bfloat16 l1 = __float2bfloat16(v[u].y - __bfloat162float(h1));
        __nv_bfloat16 l2 = __float2bfloat16(v[u].z - __bfloat162float(h2));
        __nv_bfloat16 l3 = __float2bfloat16(v[u].w - __bfloat162float(h3));
        ((__nv_bfloat162*)hi)[2 * i]     = __nv_bfloat162(h0, h1);
        ((__nv_bfloat162*)hi)[2 * i + 1] = __nv_bfloat162(h2, h3);
        ((__nv_bfloat162*)lo)[2 * i]     = __nv_bfloat162(l0, l1);
        ((__nv_bfloat162*)lo)[2 * i + 1] = __nv_bfloat162(l2, l3);
    }
}

// ---------------------------------------------------------------------------
// Tensor-core retention attention with double-buffered K/V pipeline.
// grid (32 i-tiles, 16 heads), 256 threads (8 warps, 2x4). BI=BJ=64.
// ---------------------------------------------------------------------------
static constexpr int KVBUF = 65536;            // Kh|Kl|Vh|Vl per stage
static constexpr int OQH = 0, OQL = 16384;
static constexpr int OKV = 32768;              // + b*KVBUF
static constexpr int OKH = 0, OKL = 16384, OVH = 32768, OVL = 49152;  // within KV buf
static constexpr int OSH = 163840, OSL = 172032;
static constexpr int AT_SMEM = 180224;         // 176 KB

__device__ __forceinline__ void at_load_kv(uint32_t kvbase,
                                           const __nv_bfloat16* Khg, const __nv_bfloat16* Klg,
                                           const __nv_bfloat16* Vhg, const __nv_bfloat16* Vlg,
                                           int j0, int tid) {
#pragma unroll
    for (int l = 0; l < 8; l++) {   // K hi/lo: 2 chunk-tiles of 64x64
        int idx = tid + l * 256;
        int arr = idx >> 10, ct = (idx >> 9) & 1, r = (idx >> 3) & 63, c = idx & 7;
        const __nv_bfloat16* src = (arr ? Klg : Khg) + (size_t)(j0 + r) * DIM + ct * 64 + c * 8;
        uint32_t dst = kvbase + (arr ? OKL : OKH) + ct * 8192 + r * 128 + (((c ^ (r & 7))) << 4);
        cp16(dst, src);
    }
#pragma unroll
    for (int l = 0; l < 8; l++) {   // V hi/lo: [j][128] 256B rows
        int idx = tid + l * 256;
        int arr = idx >> 10, r = (idx >> 4) & 63, dc = idx & 15;
        const __nv_bfloat16* src = (arr ? Vlg : Vhg) + (size_t)(j0 + r) * DIM + dc * 8;
        uint32_t dst = kvbase + (arr ? OVL : OVH) + r * 256 + (((dc ^ (r & 7))) << 4);
        cp16(dst, src);
    }
}

__global__ __launch_bounds__(256, 1) void retention_tc() {
    extern __shared__ char smem[];
    uint32_t sb = smem_u32(smem);

    int head = blockIdx.y;
    int it = gridDim.x - 1 - blockIdx.x;   // heaviest blocks first
    int i0 = it * 64;
    int tid = threadIdx.x, lane = tid & 31, wid = tid >> 5;
    int wm = wid & 1, wn = wid >> 1;

    const float lg0 = -3.4657359027997265f;
    const float lg1 = -6.2383246250395075f;
    float gamma = 1.0f - expf(lg0 + (lg1 - lg0) * ((float)head * (1.0f / 15.0f)));
    float log2g = log2f(gamma);
    const float scale = 0.088388347648318447f;

    const __nv_bfloat16* Qhg = g_Qhi + head * HDIM;
    const __nv_bfloat16* Qlg = g_Qlo + head * HDIM;
    const __nv_bfloat16* Khg = g_Khi + head * HDIM;
    const __nv_bfloat16* Klg = g_Klo + head * HDIM;
    const __nv_bfloat16* Vhg = g_Vhi + head * HDIM;
    const __nv_bfloat16* Vlg = g_Vlo + head * HDIM;

    int qr = lane >> 2, qc = (lane & 3) * 2;
    int a_mh = (lane >> 3) & 1, a_kh = lane >> 4, lr = lane & 7;
    int b_jl = lane >> 4, b_kh = (lane >> 3) & 1;
    int v_m = (lane >> 3) & 1, v_g = lane >> 4;

    uint32_t aOff[2]; int aR7[2];
#pragma unroll
    for (int i = 0; i < 2; i++) {
        int row = wm * 32 + i * 16 + a_mh * 8 + lr;
        aOff[i] = row * 128; aR7[i] = row & 7;
    }
    int brow = wn * 16 + b_jl * 8 + lr;
    uint32_t bOff = brow * 128; int bR7 = brow & 7;

    float colfac[2][2];
#pragma unroll
    for (int jf = 0; jf < 2; jf++)
#pragma unroll
        for (int lb = 0; lb < 2; lb++) {
            int dj = wn * 16 + jf * 8 + qc + lb;
            colfac[jf][lb] = exp2f(-log2g * (float)dj) * scale;
        }

    // prologue: Q (hi/lo) + KV tile 0, one commit group
#pragma unroll
    for (int l = 0; l < 8; l++) {
        int idx = tid + l * 256;
        int arr = idx >> 10, ct = (idx >> 9) & 1, r = (idx >> 3) & 63, c = idx & 7;
        const __nv_bfloat16* src = (arr ? Qlg : Qhg) + (size_t)(i0 + r) * DIM + ct * 64 + c * 8;
        uint32_t dst = sb + (arr ? OQL : OQH) + ct * 8192 + r * 128 + (((c ^ (r & 7))) << 4);
        cp16(dst, src);
    }
    at_load_kv(sb + OKV, Khg, Klg, Vhg, Vlg, 0, tid);
    asm volatile("cp.async.commit_group;" ::: "memory");

    float yacc[2][4][4];
#pragma unroll
    for (int i = 0; i < 2; i++)
#pragma unroll
        for (int t = 0; t < 4; t++)
#pragma unroll
            for (int q = 0; q < 4; q++) yacc[i][t][q] = 0.f;

    for (int jt = 0; jt <= it; jt++) {
        int j0 = jt * 64;
        uint32_t kvb = sb + OKV + (jt & 1) * KVBUF;

        asm volatile("cp.async.wait_group 0;" ::: "memory");
        __syncthreads();   // tile jt resident; all warps done with alt buffer

        if (jt < it) {     // prefetch jt+1 into alt buffer, overlapped with compute
            at_load_kv(sb + OKV + ((jt + 1) & 1) * KVBUF, Khg, Klg, Vhg, Vlg, j0 + 64, tid);
            asm volatile("cp.async.commit_group;" ::: "memory");
        }

        // ---- stage 1: S = Q.K^T (3-pass hi/lo) ----
        float acc1[2][2][4];
#pragma unroll
        for (int i = 0; i < 2; i++)
#pragma unroll
            for (int j = 0; j < 2; j++)
#pragma unroll
                for (int q = 0; q < 4; q++) acc1[i][j][q] = 0.f;

#pragma unroll
        for (int ct = 0; ct < 2; ct++) {
#pragma unroll
            for (int ks = 0; ks < 4; ks++) {
                int ca = ks * 2 + a_kh;
                int cb = ks * 2 + b_kh;
                uint32_t qh[2][4], ql[2][4], bh[4], bl[4];
#pragma unroll
                for (int i = 0; i < 2; i++) {
                    ldx4(qh[i], sb + OQH + ct * 8192 + aOff[i] + (((uint32_t)(ca ^ aR7[i])) << 4));
                    ldx4(ql[i], sb + OQL + ct * 8192 + aOff[i] + (((uint32_t)(ca ^ aR7[i])) << 4));
                }
                ldx4(bh, kvb + OKH + ct * 8192 + bOff + (((uint32_t)(cb ^ bR7)) << 4));
                ldx4(bl, kvb + OKL + ct * 8192 + bOff + (((uint32_t)(cb ^ bR7)) << 4));
#pragma unroll
                for (int i = 0; i < 2; i++)
#pragma unroll
                    for (int j = 0; j < 2; j++) {
                        mma16816(acc1[i][j], qh[i], bh[2 * j], bh[2 * j + 1]);
                        mma16816(acc1[i][j], qh[i], bl[2 * j], bl[2 * j + 1]);
                        mma16816(acc1[i][j], ql[i], bh[2 * j], bh[2 * j + 1]);
                    }
            }
        }

        // ---- decay, mask, split -> S smem ----
        float rowfac[2][2];
#pragma unroll
        for (int i = 0; i < 2; i++)
#pragma unroll
            for (int h = 0; h < 2; h++) {
                int rrel = i0 - j0 + wm * 32 + i * 16 + qr + h * 8;
                rowfac[i][h] = exp2f(log2g * (float)rrel);
            }
#pragma unroll
        for (int i = 0; i < 2; i++)
#pragma unroll
            for (int j = 0; j < 2; j++)
#pragma unroll
                for (int h = 0; h < 2; h++) {
                    int row = wm * 32 + i * 16 + qr + h * 8;
                    int col = wn * 16 + j * 8 + qc;
                    int diff0 = (i0 + row) - (j0 + col);
                    float v0 = (diff0 >= 0) ? acc1[i][j][h * 2 + 0] * rowfac[i][h] * colfac[j][0] : 0.f;
                    float v1 = (diff0 >= 1) ? acc1[i][j][h * 2 + 1] * rowfac[i][h] * colfac[j][1] : 0.f;
                    __nv_bfloat16 h0 = __float2bfloat16(v0), h1 = __float2bfloat16(v1);
                    __nv_bfloat16 l0 = __float2bfloat16(v0 - __bfloat162float(h0));
                    __nv_bfloat16 l1 = __float2bfloat16(v1 - __bfloat162float(h1));
                    uint32_t off = row * 128 + ((((col >> 3) ^ (row & 7))) << 4) + (col & 7) * 2;
                    *(__nv_bfloat162*)(smem + OSH + off) = __nv_bfloat162(h0, h1);
                    *(__nv_bfloat162*)(smem + OSL + off) = __nv_bfloat162(l0, l1);
                }
        __syncthreads();

        // ---- stage 2: Y += S.V (3-pass hi/lo) ----
#pragma unroll
        for (int ks = 0; ks < 4; ks++) {
            int ca = ks * 2 + a_kh;
            uint32_t sh[2][4], sl[2][4], vh[2][4], vl[2][4];
#pragma unroll
            for (int i = 0; i < 2; i++) {
                ldx4(sh[i], sb + OSH + aOff[i] + (((uint32_t)(ca ^ aR7[i])) << 4));
                ldx4(sl[i], sb + OSL + aOff[i] + (((uint32_t)(ca ^ aR7[i])) << 4));
            }
            int vrow = ks * 16 + v_m * 8 + lr;
#pragma unroll
            for (int g = 0; g < 2; g++) {
                int dc = wn * 4 + g * 2 + v_g;
                uint32_t vo = vrow * 256 + (((uint32_t)(dc ^ (vrow & 7))) << 4);
                ldx4t(vh[g], kvb + OVH + vo);
                ldx4t(vl[g], kvb + OVL + vo);
            }
#pragma unroll
            for (int i = 0; i < 2; i++)
#pragma unroll
                for (int t = 0; t < 4; t++) {
                    int g = t >> 1, s2 = (t & 1) * 2;
                    mma16816(yacc[i][t], sh[i], vh[g][s2], vh[g][s2 + 1]);
                    mma16816(yacc[i][t], sh[i], vl[g][s2], vl[g][s2 + 1]);
                    mma16816(yacc[i][t], sl[i], vh[g][s2], vh[g][s2 + 1]);
                }
        }
    }

    // epilogue -> g_Y fp32
#pragma unroll
    for (int i = 0; i < 2; i++) {
        int row = i0 + wm * 32 + i * 16 + qr;
#pragma unroll
        for (int t = 0; t < 4; t++) {
            float* yp = g_Y + (size_t)row * DIM + head * HDIM + wn * 32 + t * 8 + qc;
            *(float2*)yp = make_float2(yacc[i][t][0], yacc[i][t][1]);
            *(float2*)(yp + 8 * DIM) = make_float2(yacc[i][t][2], yacc[i][t][3]);
        }
    }
}

// ---------------------------------------------------------------------------
// LayerNorm(Y) * silu(G) -> bf16 hi + lo arrays
// ---------------------------------------------------------------------------
__global__ __launch_bounds__(256) void ln_silu_gate(const float* __restrict__ lnw,
                                                    const float* __restrict__ lnb,
                                                    __nv_bfloat16* __restrict__ ohi,
                                                    __nv_bfloat16* __restrict__ olo) {
    int row = blockIdx.x;
    const float* y = g_Y + (size_t)row * DIM;
    const float* g = g_G + (size_t)row * DIM;
    int tid = threadIdx.x;

    float vals[8];
    float s = 0.f, ss = 0.f;
#pragma unroll
    for (int i = 0; i < 2; i++) {
        float4 v = *(const float4*)(y + tid * 4 + i * 1024);
        vals[i * 4 + 0] = v.x; vals[i * 4 + 1] = v.y;
        vals[i * 4 + 2] = v.z; vals[i * 4 + 3] = v.w;
        s += v.x + v.y + v.z + v.w;
        ss += v.x * v.x + v.y * v.y + v.z * v.z + v.w * v.w;
    }
#pragma unroll
    for (int off = 16; off > 0; off >>= 1) {
        s += __shfl_xor_sync(0xFFFFFFFFu, s, off);
        ss += __shfl_xor_sync(0xFFFFFFFFu, ss, off);
    }
    __shared__ float rs[8], rss[8];
    if ((tid & 31) == 0) { rs[tid >> 5] = s; rss[tid >> 5] = ss; }
    __syncthreads();
    s = 0.f; ss = 0.f;
#pragma unroll
    for (int i = 0; i < 8; i++) { s += rs[i]; ss += rss[i]; }

    float mu = s * (1.0f / DIM);
    float var = ss * (1.0f / DIM) - mu * mu;
    float rstd = rsqrtf(var + 1e-5f);

#pragma unroll
    for (int i = 0; i < 2; i++) {
        int c0 = tid * 4 + i * 1024;
        float4 gv = *(const float4*)(g + c0);
        float4 wv = *(const float4*)(lnw + c0);
        float4 bv = *(const float4*)(lnb + c0);
        float o[4];
        o[0] = ((vals[i * 4 + 0] - mu) * rstd * wv.x + bv.x) * (gv.x / (1.0f + expf(-gv.x)));
        o[1] = ((vals[i * 4 + 1] - mu) * rstd * wv.y + bv.y) * (gv.y / (1.0f + expf(-gv.y)));
        o[2] = ((vals[i * 4 + 2] - mu) * rstd * wv.z + bv.z) * (gv.z / (1.0f + expf(-gv.z)));
        o[3] = ((vals[i * 4 + 3] - mu) * rstd * wv.w + bv.w) * (gv.w / (1.0f + expf(-gv.w)));
        __nv_bfloat16 h[4], l[4];
#pragma unroll
        for (int j = 0; j < 4; j++) {
            h[j] = __float2bfloat16(o[j]);
            l[j] = __float2bfloat16(o[j] - __bfloat162float(h[j]));
        }
        size_t base = (size_t)row * DIM + c0;
        *(__nv_bfloat162*)(ohi + base)     = __nv_bfloat162(h[0], h[1]);
        *(__nv_bfloat162*)(ohi + base + 2) = __nv_bfloat162(h[2], h[3]);
        *(__nv_bfloat162*)(olo + base)     = __nv_bfloat162(l[0], l[1]);
        *(__nv_bfloat162*)(olo + base + 2) = __nv_bfloat162(l[2], l[3]);
    }
}

// ---------------------------------------------------------------------------
extern "C" void kernel_launch(void* const* d_in, const int* in_sizes, int n_in,
                              void* d_out, int out_size) {
    const float* x   = (const float*)d_in[0];
    const float* wq  = (const float*)d_in[1];
    const float* wk  = (const float*)d_in[2];
    const float* wv  = (const float*)d_in[3];
    const float* wg  = (const float*)d_in[4];
    const float* wo  = (const float*)d_in[5];
    const float* lnw = (const float*)d_in[6];
    const float* lnb = (const float*)d_in[7];
    float* out = (float*)d_out;

    float *G, *Y;
    __nv_bfloat16 *xhi, *xlo, *ahi, *alo;
    __nv_bfloat16 *whi[5], *wlo[5];
    __nv_bfloat16 *qhi, *qlo, *khi, *klo, *vhi, *vlo;
    cudaGetSymbolAddress((void**)&G, g_G);
    cudaGetSymbolAddress((void**)&Y, g_Y);
    cudaGetSymbolAddress((void**)&xhi, g_xhi);  cudaGetSymbolAddress((void**)&xlo, g_xlo);
    cudaGetSymbolAddress((void**)&ahi, g_ahi);  cudaGetSymbolAddress((void**)&alo, g_alo);
    cudaGetSymbolAddress((void**)&whi[0], g_wqhi); cudaGetSymbolAddress((void**)&wlo[0], g_wqlo);
    cudaGetSymbolAddress((void**)&whi[1], g_wkhi); cudaGetSymbolAddress((void**)&wlo[1], g_wklo);
    cudaGetSymbolAddress((void**)&whi[2], g_wvhi); cudaGetSymbolAddress((void**)&wlo[2], g_wvlo);
    cudaGetSymbolAddress((void**)&whi[3], g_wghi); cudaGetSymbolAddress((void**)&wlo[3], g_wglo);
    cudaGetSymbolAddress((void**)&whi[4], g_wohi); cudaGetSymbolAddress((void**)&wlo[4], g_wolo);
    cudaGetSymbolAddress((void**)&qhi, g_Qhi); cudaGetSymbolAddress((void**)&qlo, g_Qlo);
    cudaGetSymbolAddress((void**)&khi, g_Khi); cudaGetSymbolAddress((void**)&klo, g_Klo);
    cudaGetSymbolAddress((void**)&vhi, g_Vhi); cudaGetSymbolAddress((void**)&vlo, g_Vlo);

    cudaFuncSetAttribute(gemm3, cudaFuncAttributeMaxDynamicSharedMemorySize, GEMM_SMEM);
    cudaFuncSetAttribute(retention_tc, cudaFuncAttributeMaxDynamicSharedMemorySize, AT_SMEM);

    const int cvt_blocks = SEQ * DIM / 4 / 1024;   // 1024
    cvt_split<<<cvt_blocks, 256>>>(x,  xhi,    xlo);
    cvt_split<<<cvt_blocks, 256>>>(wq, whi[0], wlo[0]);
    cvt_split<<<cvt_blocks, 256>>>(wk, whi[1], wlo[1]);
    cvt_split<<<cvt_blocks, 256>>>(wv, whi[2], wlo[2]);
    cvt_split<<<cvt_blocks, 256>>>(wg, whi[3], wlo[3]);
    cvt_split<<<cvt_blocks, 256>>>(wo, whi[4], wlo[4]);

    dim3 gg(DIM / GBN, SEQ / GBM);  // (8, 16) = 128 CTAs, single wave
    gemm3<<<gg, 256, GEMM_SMEM>>>(xhi, xlo, whi[0], wlo[0], nullptr, qhi, qlo, 1);
    gemm3<<<gg, 256, GEMM_SMEM>>>(xhi, xlo, whi[1], wlo[1], nullptr, khi, klo, 1);
    gemm3<<<gg, 256, GEMM_SMEM>>>(xhi, xlo, whi[2], wlo[2], nullptr, vhi, vlo, 1);
    gemm3<<<gg, 256, GEMM_SMEM>>>(xhi, xlo, whi[3], wlo[3], G, nullptr, nullptr, 0);

    retention_tc<<<dim3(SEQ / 64, NH), 256, AT_SMEM>>>();

    ln_silu_gate<<<SEQ, 256>>>(lnw, lnb, ahi, alo);

    gemm3<<<gg, 256, GEMM_SMEM>>>(ahi, alo, whi[4], wlo[4], out, nullptr, nullptr, 0);
}